// round 9
// baseline (speedup 1.0000x reference)
#include <cuda_runtime.h>
#include <math.h>

#define B     8
#define T     2048
#define DM    64
#define NH    6
#define HS    10
#define BT    (B*T)        // 16384
#define BH    (B*NH)       // 48

typedef unsigned long long u64;

// ---------------- packed f32x2 helpers ----------------
__device__ __forceinline__ u64 f2_mul(u64 a, u64 b) {
    u64 d; asm("mul.rn.f32x2 %0,%1,%2;" : "=l"(d) : "l"(a), "l"(b)); return d;
}
__device__ __forceinline__ u64 f2_fma(u64 a, u64 b, u64 c) {
    u64 d; asm("fma.rn.f32x2 %0,%1,%2,%3;" : "=l"(d) : "l"(a), "l"(b), "l"(c)); return d;
}
__device__ __forceinline__ u64 f2_add(u64 a, u64 b) {
    u64 d; asm("add.rn.f32x2 %0,%1,%2;" : "=l"(d) : "l"(a), "l"(b)); return d;
}
__device__ __forceinline__ u64 pk(float lo, float hi) {
    u64 r; asm("mov.b64 %0,{%1,%2};" : "=l"(r) : "f"(lo), "f"(hi)); return r;
}
__device__ __forceinline__ void upk(float& lo, float& hi, u64 a) {
    asm("mov.b64 {%0,%1},%2;" : "=f"(lo), "=f"(hi) : "l"(a));
}
__device__ __forceinline__ float ex2f(float x) {
    float r; asm("ex2.approx.f32 %0,%1;" : "=f"(r) : "f"(x)); return r;
}

// ---------------- scratch ----------------
__device__ __align__(16) float g_q [BH * T * 12];
__device__ __align__(16) float g_kp[BH * (T/2) * 20];   // [bh][t/2][d=0..9][2]
__device__ __align__(16) float g_vp[BH * (T/2) * 20];
__device__ __align__(16) float g_attn[BT * 60];

// ================= Kernel 1: QKV projection =================
// 128 rows/block, 3 heads/block (head-group split): grid 256, 256 threads.
__global__ __launch_bounds__(256, 2) void k_qkv(const float* __restrict__ x,
                                                const float* __restrict__ Wqkv) {
    __shared__ __align__(16) float Wsm[90 * 64];   // e-major for 3 heads: [(hh*30+e)][d]
    const int tid    = threadIdx.x;
    const int r      = tid & 127;
    const int half   = tid >> 7;
    const int rowblk = blockIdx.x >> 1;
    const int hg     = blockIdx.x & 1;
    const int hbase  = hg * 3;
    const int row    = rowblk * 128 + r;

    // transpose 3 heads of W: src = ((hbase+h)*64 + d)*30 + e
    for (int idx = tid; idx < 3*30*64; idx += 256) {
        int h = idx / 1920; int rem = idx % 1920;
        int e = rem / 64;   int d   = rem % 64;
        Wsm[idx] = Wqkv[((hbase + h)*64 + d)*30 + e];
    }
    __syncthreads();

    u64 xp[32];
    {
        const ulonglong2* gx = (const ulonglong2*)(x + row * 64);
        #pragma unroll
        for (int i = 0; i < 16; ++i) { ulonglong2 u = gx[i]; xp[2*i] = u.x; xp[2*i+1] = u.y; }
    }

    const int b = row >> 11, t = row & 2047;
    const int tp = t >> 1, par = t & 1;
    const int ebase = half * 15;

    for (int hh = 0; hh < 3; ++hh) {
        float f[15];
        #pragma unroll
        for (int e = 0; e < 15; ++e) {
            const ulonglong2* w2 = (const ulonglong2*)&Wsm[(hh*30 + ebase + e)*64];
            u64 c0, c1, c2, c3;
            {
                ulonglong2 wa = w2[0], wb = w2[1];
                c0 = f2_mul(xp[0], wa.x); c1 = f2_mul(xp[1], wa.y);
                c2 = f2_mul(xp[2], wb.x); c3 = f2_mul(xp[3], wb.y);
            }
            #pragma unroll
            for (int g = 1; g < 8; ++g) {
                ulonglong2 wa = w2[2*g], wb = w2[2*g+1];
                c0 = f2_fma(xp[4*g+0], wa.x, c0);
                c1 = f2_fma(xp[4*g+1], wa.y, c1);
                c2 = f2_fma(xp[4*g+2], wb.x, c2);
                c3 = f2_fma(xp[4*g+3], wb.y, c3);
            }
            c0 = f2_add(c0, c1); c2 = f2_add(c2, c3); c0 = f2_add(c0, c2);
            float l, hvv; upk(l, hvv, c0);
            f[e] = l + hvv;
        }
        const int bh   = b*NH + hbase + hh;
        const int kvbs = (bh*(T/2) + tp) * 20;
        if (half == 0) {
            const int off = (bh*T + t) * 12;
            float4* oq = (float4*)&g_q[off];
            oq[0] = make_float4(f[0], f[1], f[2], f[3]);
            oq[1] = make_float4(f[4], f[5], f[6], f[7]);
            oq[2] = make_float4(f[8], f[9], 0.f, 0.f);
            #pragma unroll
            for (int d = 0; d < 5; ++d) g_kp[kvbs + 2*d + par] = f[10 + d];
        } else {
            #pragma unroll
            for (int d = 0; d < 5; ++d) g_kp[kvbs + 2*(5+d) + par] = f[d];
            #pragma unroll
            for (int d = 0; d < 10; ++d) g_vp[kvbs + 2*d + par] = f[5 + d];
        }
    }
}

// ================= Kernel 2: causal flash attention =================
// s-packed f32x2 + 2 adjacent q-rows per thread sharing each K/V smem read.
// grid 384 (bx desc for LPT), 128 threads; thread owns rows (2*tid, 2*tid+1)
// of a 256-row tile. rel0 is always even, rel1 = rel0+1 odd -> one clean
// diagonal clause per chunk.
#define ATT_LOAD                                                               \
    const ulonglong2* kp2 = (const ulonglong2*)(ksP + sp*20);                  \
    const ulonglong2* vp2 = (const ulonglong2*)(vsP + sp*20);                  \
    ulonglong2 kA=kp2[0], kB=kp2[1], kC=kp2[2], kD=kp2[3], kE=kp2[4];          \
    ulonglong2 vA=vp2[0], vB=vp2[1], vC=vp2[2], vD=vp2[3], vE=vp2[4];

#define ATT_ROW(qp, acc, ssp, HALF)                                            \
    {   u64 s0 = f2_mul(qp[0], kA.x), s1 = f2_mul(qp[1], kA.y);                \
        s0 = f2_fma(qp[2], kB.x, s0); s1 = f2_fma(qp[3], kB.y, s1);            \
        s0 = f2_fma(qp[4], kC.x, s0); s1 = f2_fma(qp[5], kC.y, s1);            \
        s0 = f2_fma(qp[6], kD.x, s0); s1 = f2_fma(qp[7], kD.y, s1);            \
        s0 = f2_fma(qp[8], kE.x, s0); s1 = f2_fma(qp[9], kE.y, s1);            \
        s0 = f2_add(s0, s1);                                                   \
        float dl, dh; upk(dl, dh, s0);                                         \
        float pl = ex2f(dl);                                                   \
        float ph = (HALF) ? 0.f : ex2f(dh);                                    \
        u64 pp = pk(pl, ph);                                                   \
        ssp = f2_add(ssp, pp);                                                 \
        acc[0]=f2_fma(pp,vA.x,acc[0]); acc[1]=f2_fma(pp,vA.y,acc[1]);          \
        acc[2]=f2_fma(pp,vB.x,acc[2]); acc[3]=f2_fma(pp,vB.y,acc[3]);          \
        acc[4]=f2_fma(pp,vC.x,acc[4]); acc[5]=f2_fma(pp,vC.y,acc[5]);          \
        acc[6]=f2_fma(pp,vD.x,acc[6]); acc[7]=f2_fma(pp,vD.y,acc[7]);          \
        acc[8]=f2_fma(pp,vE.x,acc[8]); acc[9]=f2_fma(pp,vE.y,acc[9]); }

__global__ __launch_bounds__(128, 3) void k_attn() {
    __shared__ __align__(16) float ksm[2][1280];
    __shared__ __align__(16) float vsm[2][1280];
    const int tid = threadIdx.x;
    const int bx  = 7 - (int)(blockIdx.x / 48);   // heavy tiles first (LPT)
    const int bh  = blockIdx.x % 48;
    const int r0  = bx*256 + 2*tid;               // even row; r1 = r0+1

    const float SC = 0.31622776601683794f * 1.4426950408889634f; // rsqrt(10)*log2e
    u64 qa[10], qb[10];
    {
        const float4* g0 = (const float4*)&g_q[(bh*T + r0)*12];
        const float4* g1 = (const float4*)&g_q[(bh*T + r0 + 1)*12];
        float4 a0 = g0[0], a1 = g0[1], a2 = g0[2];
        float4 b0 = g1[0], b1 = g1[1], b2 = g1[2];
        qa[0]=pk(a0.x*SC,a0.x*SC); qa[1]=pk(a0.y*SC,a0.y*SC);
        qa[2]=pk(a0.z*SC,a0.z*SC); qa[3]=pk(a0.w*SC,a0.w*SC);
        qa[4]=pk(a1.x*SC,a1.x*SC); qa[5]=pk(a1.y*SC,a1.y*SC);
        qa[6]=pk(a1.z*SC,a1.z*SC); qa[7]=pk(a1.w*SC,a1.w*SC);
        qa[8]=pk(a2.x*SC,a2.x*SC); qa[9]=pk(a2.y*SC,a2.y*SC);
        qb[0]=pk(b0.x*SC,b0.x*SC); qb[1]=pk(b0.y*SC,b0.y*SC);
        qb[2]=pk(b0.z*SC,b0.z*SC); qb[3]=pk(b0.w*SC,b0.w*SC);
        qb[4]=pk(b1.x*SC,b1.x*SC); qb[5]=pk(b1.y*SC,b1.y*SC);
        qb[6]=pk(b1.z*SC,b1.z*SC); qb[7]=pk(b1.w*SC,b1.w*SC);
        qb[8]=pk(b2.x*SC,b2.x*SC); qb[9]=pk(b2.y*SC,b2.y*SC);
    }
    u64 acc0[10], acc1[10];
    #pragma unroll
    for (int i = 0; i < 10; ++i) { acc0[i] = 0ull; acc1[i] = 0ull; }
    u64 ssa = 0ull, ssb = 0ull;

    const int nc = 2*bx + 2;
    const float4* srcK0 = (const float4*)&g_kp[(size_t)(bh*(T/2)) * 20];
    const float4* srcV0 = (const float4*)&g_vp[(size_t)(bh*(T/2)) * 20];

    // prologue: chunk 0 -> buffer 0 (K: 320 float4, V: 320 float4)
    for (int i = tid; i < 640; i += 128) {
        float4 v = (i < 320) ? srcK0[i] : srcV0[i - 320];
        if (i < 320) ((float4*)ksm[0])[i] = v; else ((float4*)vsm[0])[i - 320] = v;
    }
    __syncthreads();

    for (int c = 0; c < nc; ++c) {
        const int cb = c & 1;
        float4 st0, st1, st2, st3, st4;
        const bool more = (c + 1 < nc);
        if (more) {
            const float4* sK = srcK0 + (c+1)*320;
            const float4* sV = srcV0 + (c+1)*320;
            st0 = sK[tid];
            st1 = sK[tid + 128];
            st2 = (tid < 64) ? sK[tid + 256] : sV[tid - 64];
            st3 = sV[tid + 64];
            st4 = sV[tid + 192];
        }

        const float* ksP = ksm[cb];
        const float* vsP = vsm[cb];
        const int rel0 = r0 - (c << 7);           // always even
        int nfull = rel0 >> 1;
        nfull = nfull < 0 ? 0 : (nfull > 64 ? 64 : nfull);
        #pragma unroll 2
        for (int sp = 0; sp < nfull; ++sp) {
            ATT_LOAD
            ATT_ROW(qa, acc0, ssa, false)
            ATT_ROW(qb, acc1, ssb, false)
        }
        if ((unsigned)rel0 < 128u) {
            const int sp = rel0 >> 1;
            ATT_LOAD
            ATT_ROW(qb, acc1, ssb, false)   // row1: pair (rel0, rel0+1) fully visible
            ATT_ROW(qa, acc0, ssa, true)    // row0: only s=rel0 visible
        }

        if (more) {
            float4* dK = (float4*)ksm[cb ^ 1];
            float4* dV = (float4*)vsm[cb ^ 1];
            dK[tid] = st0;
            dK[tid + 128] = st1;
            if (tid < 64) dK[tid + 256] = st2; else dV[tid - 64] = st2;
            dV[tid + 64] = st3;
            dV[tid + 192] = st4;
        }
        __syncthreads();
    }

    const int b = bh / NH, h = bh % NH;
    {
        float sl, sh; upk(sl, sh, ssa);
        const float inv = 1.f / (sl + sh);
        float* o = &g_attn[(b*T + r0)*60 + h*10];
        #pragma unroll
        for (int d = 0; d < 10; d += 2) {
            float l0, h0, l1, h1;
            upk(l0, h0, acc0[d]); upk(l1, h1, acc0[d+1]);
            *(float2*)&o[d] = make_float2((l0 + h0)*inv, (l1 + h1)*inv);
        }
    }
    {
        float sl, sh; upk(sl, sh, ssb);
        const float inv = 1.f / (sl + sh);
        float* o = &g_attn[(b*T + r0 + 1)*60 + h*10];
        #pragma unroll
        for (int d = 0; d < 10; d += 2) {
            float l0, h0, l1, h1;
            upk(l0, h0, acc1[d]); upk(l1, h1, acc1[d+1]);
            *(float2*)&o[d] = make_float2((l0 + h0)*inv, (l1 + h1)*inv);
        }
    }
}

// ================= Kernel 3: fused proj + LN1 + FFN + LN2 =================
#define HSP 260
__global__ __launch_bounds__(256) void k_tail(const float* __restrict__ x,
                                              const float* __restrict__ Wp,
                                              const float* __restrict__ bp,
                                              const float* __restrict__ g1,
                                              const float* __restrict__ b1ln,
                                              const float* __restrict__ W1,
                                              const float* __restrict__ bb1,
                                              const float* __restrict__ W2,
                                              const float* __restrict__ bb2,
                                              const float* __restrict__ g2,
                                              const float* __restrict__ b2ln,
                                              float* __restrict__ out) {
    extern __shared__ __align__(16) float sm[];
    float* atn = sm;                 // 32*60
    float* xs  = sm + 32*60;         // 32*64
    float* hs  = sm + 32*60 + 32*64; // 32*260

    const int tid  = threadIdx.x;
    const int row0 = blockIdx.x * 32;

    for (int idx = tid; idx < 32*60; idx += 256) atn[idx] = g_attn[row0*60 + idx];
    __syncthreads();

    {
        const int r  = tid >> 3;
        const int cg = tid & 7;
        const int c0 = cg * 8;
        u64 pa0 = 0, pa1 = 0, pa2 = 0, pa3 = 0;
        #pragma unroll 4
        for (int i = 0; i < 60; ++i) {
            float a = atn[r*60 + i];
            u64 ap = pk(a, a);
            const ulonglong2* w2 = (const ulonglong2*)&Wp[i*64 + c0];
            ulonglong2 wA = w2[0], wB = w2[1];
            pa0 = f2_fma(ap, wA.x, pa0); pa1 = f2_fma(ap, wA.y, pa1);
            pa2 = f2_fma(ap, wB.x, pa2); pa3 = f2_fma(ap, wB.y, pa3);
        }
        {
            const ulonglong2* bb = (const ulonglong2*)&bp[c0];
            ulonglong2 bA = bb[0], bB = bb[1];
            pa0 = f2_add(pa0, bA.x); pa1 = f2_add(pa1, bA.y);
            pa2 = f2_add(pa2, bB.x); pa3 = f2_add(pa3, bB.y);
        }
        float sa[8];
        upk(sa[0], sa[1], pa0); upk(sa[2], sa[3], pa1);
        upk(sa[4], sa[5], pa2); upk(sa[6], sa[7], pa3);
        float s = 0.f, qq = 0.f;
        #pragma unroll
        for (int i = 0; i < 8; ++i) { s += sa[i]; qq = fmaf(sa[i], sa[i], qq); }
        #pragma unroll
        for (int m = 4; m; m >>= 1) {
            s  += __shfl_xor_sync(0xffffffffu, s, m);
            qq += __shfl_xor_sync(0xffffffffu, qq, m);
        }
        const float mu = s * (1.f/64.f);
        const float ri = rsqrtf(qq * (1.f/64.f) - mu*mu + 1e-5f);
        const float4* xr = (const float4*)(x + (row0 + r)*64 + c0);
        const float4* gg = (const float4*)(g1 + c0);
        const float4* bb = (const float4*)(b1ln + c0);
        float4 xA = xr[0], xB = xr[1], gA = gg[0], gB = gg[1], bA = bb[0], bB = bb[1];
        float4 o0, o1;
        o0.x = xA.x + (sa[0]-mu)*ri*gA.x + bA.x;  o0.y = xA.y + (sa[1]-mu)*ri*gA.y + bA.y;
        o0.z = xA.z + (sa[2]-mu)*ri*gA.z + bA.z;  o0.w = xA.w + (sa[3]-mu)*ri*gA.w + bA.w;
        o1.x = xB.x + (sa[4]-mu)*ri*gB.x + bB.x;  o1.y = xB.y + (sa[5]-mu)*ri*gB.y + bB.y;
        o1.z = xB.z + (sa[6]-mu)*ri*gB.z + bB.z;  o1.w = xB.w + (sa[7]-mu)*ri*gB.w + bB.w;
        *(float4*)&xs[r*64 + c0]     = o0;
        *(float4*)&xs[r*64 + c0 + 4] = o1;
    }
    __syncthreads();

    const int w  = tid >> 5;
    const int co = tid & 31;
    const int rb = w * 4;

    {
        const int c0 = co * 8;
        u64 ac[4][4];
        #pragma unroll
        for (int r = 0; r < 4; ++r)
            #pragma unroll
            for (int j = 0; j < 4; ++j) ac[r][j] = 0ull;

        for (int d = 0; d < 64; d += 4) {
            float4 xv[4];
            #pragma unroll
            for (int r = 0; r < 4; ++r) xv[r] = *(const float4*)&xs[(rb+r)*64 + d];
            #pragma unroll
            for (int dd = 0; dd < 4; ++dd) {
                const ulonglong2* w1p = (const ulonglong2*)&W1[(d+dd)*256 + c0];
                ulonglong2 wA = w1p[0], wB = w1p[1];
                #pragma unroll
                for (int r = 0; r < 4; ++r) {
                    float xvv = ((const float*)&xv[r])[dd];
                    u64 px = pk(xvv, xvv);
                    ac[r][0] = f2_fma(px, wA.x, ac[r][0]);
                    ac[r][1] = f2_fma(px, wA.y, ac[r][1]);
                    ac[r][2] = f2_fma(px, wB.x, ac[r][2]);
                    ac[r][3] = f2_fma(px, wB.y, ac[r][3]);
                }
            }
        }
        const ulonglong2* bbp = (const ulonglong2*)&bb1[c0];
        ulonglong2 bA = bbp[0], bB = bbp[1];
        #pragma unroll
        for (int r = 0; r < 4; ++r) {
            ac[r][0] = f2_add(ac[r][0], bA.x); ac[r][1] = f2_add(ac[r][1], bA.y);
            ac[r][2] = f2_add(ac[r][2], bB.x); ac[r][3] = f2_add(ac[r][3], bB.y);
            float h[8];
            upk(h[0], h[1], ac[r][0]); upk(h[2], h[3], ac[r][1]);
            upk(h[4], h[5], ac[r][2]); upk(h[6], h[7], ac[r][3]);
            #pragma unroll
            for (int j = 0; j < 8; ++j)
                h[j] = 0.5f * h[j] * (1.f + erff(h[j] * 0.70710678118654752f));
            *(float4*)&hs[(rb+r)*HSP + c0]     = make_float4(h[0], h[1], h[2], h[3]);
            *(float4*)&hs[(rb+r)*HSP + c0 + 4] = make_float4(h[4], h[5], h[6], h[7]);
        }
    }
    __syncthreads();

    {
        const int c = 2 * co;
        u64 bacc[4];
        #pragma unroll
        for (int r = 0; r < 4; ++r) bacc[r] = 0ull;

        for (int i = 0; i < 256; i += 4) {
            float4 hv[4];
            #pragma unroll
            for (int r = 0; r < 4; ++r) hv[r] = *(const float4*)&hs[(rb+r)*HSP + i];
            #pragma unroll
            for (int ii = 0; ii < 4; ++ii) {
                u64 wv = *(const u64*)&W2[(i+ii)*64 + c];
                #pragma unroll
                for (int r = 0; r < 4; ++r) {
                    float hvv = ((const float*)&hv[r])[ii];
                    u64 ph = pk(hvv, hvv);
                    bacc[r] = f2_fma(ph, wv, bacc[r]);
                }
            }
        }
        u64 b2v = *(const u64*)&bb2[c];
        float fv[4][2];
        #pragma unroll
        for (int r = 0; r < 4; ++r) {
            bacc[r] = f2_add(bacc[r], b2v);
            upk(fv[r][0], fv[r][1], bacc[r]);
        }
        float mu[4], ri[4];
        #pragma unroll
        for (int r = 0; r < 4; ++r) {
            float s = fv[r][0] + fv[r][1];
            float qq = fmaf(fv[r][0], fv[r][0], fv[r][1]*fv[r][1]);
            #pragma unroll
            for (int m = 16; m; m >>= 1) {
                s  += __shfl_xor_sync(0xffffffffu, s, m);
                qq += __shfl_xor_sync(0xffffffffu, qq, m);
            }
            mu[r] = s * (1.f/64.f);
            ri[r] = rsqrtf(qq * (1.f/64.f) - mu[r]*mu[r] + 1e-5f);
        }
        float2 g2v = *(const float2*)&g2[c];
        float2 b2l = *(const float2*)&b2ln[c];
        #pragma unroll
        for (int r = 0; r < 4; ++r) {
            float2 xv = *(const float2*)&xs[(rb+r)*64 + c];
            float2 o;
            o.x = xv.x + (fv[r][0]-mu[r])*ri[r]*g2v.x + b2l.x;
            o.y = xv.y + (fv[r][1]-mu[r])*ri[r]*g2v.y + b2l.y;
            *(float2*)&out[(row0 + rb + r)*64 + c] = o;
        }
    }
}

// ===========================================================================
extern "C" void kernel_launch(void* const* d_in, const int* in_sizes, int n_in,
                              void* d_out, int out_size) {
    const float* x     = (const float*)d_in[0];
    const float* Wqkv  = (const float*)d_in[1];
    const float* Wproj = (const float*)d_in[2];
    const float* bproj = (const float*)d_in[3];
    const float* ln1g  = (const float*)d_in[4];
    const float* ln1b  = (const float*)d_in[5];
    const float* W1    = (const float*)d_in[6];
    const float* b1    = (const float*)d_in[7];
    const float* W2    = (const float*)d_in[8];
    const float* b2    = (const float*)d_in[9];
    const float* ln2g  = (const float*)d_in[10];
    const float* ln2b  = (const float*)d_in[11];
    float* out = (float*)d_out;

    k_qkv<<<BT/64, 256>>>(x, Wqkv);
    k_attn<<<8*48, 128>>>();
    const int smemTail = (32*60 + 32*64 + 32*HSP) * (int)sizeof(float);
    k_tail<<<BT/32, 256, smemTail>>>(x, Wproj, bproj, ln1g, ln1b,
                                     W1, b1, W2, b2, ln2g, ln2b, out);
}

// round 17
// speedup vs baseline: 1.0310x; 1.0310x over previous
#include <cuda_runtime.h>
#include <math.h>

#define B     8
#define T     2048
#define DM    64
#define NH    6
#define HS    10
#define BT    (B*T)        // 16384
#define BH    (B*NH)       // 48

typedef unsigned long long u64;

// ---------------- packed f32x2 helpers ----------------
__device__ __forceinline__ u64 f2_mul(u64 a, u64 b) {
    u64 d; asm("mul.rn.f32x2 %0,%1,%2;" : "=l"(d) : "l"(a), "l"(b)); return d;
}
__device__ __forceinline__ u64 f2_fma(u64 a, u64 b, u64 c) {
    u64 d; asm("fma.rn.f32x2 %0,%1,%2,%3;" : "=l"(d) : "l"(a), "l"(b), "l"(c)); return d;
}
__device__ __forceinline__ u64 f2_add(u64 a, u64 b) {
    u64 d; asm("add.rn.f32x2 %0,%1,%2;" : "=l"(d) : "l"(a), "l"(b)); return d;
}
__device__ __forceinline__ u64 pk(float lo, float hi) {
    u64 r; asm("mov.b64 %0,{%1,%2};" : "=l"(r) : "f"(lo), "f"(hi)); return r;
}
__device__ __forceinline__ void upk(float& lo, float& hi, u64 a) {
    asm("mov.b64 {%0,%1},%2;" : "=f"(lo), "=f"(hi) : "l"(a));
}
__device__ __forceinline__ float ex2f(float x) {
    float r; asm("ex2.approx.f32 %0,%1;" : "=f"(r) : "f"(x)); return r;
}

// ---------------- scratch ----------------
__device__ __align__(16) float g_q [BH * T * 12];
__device__ __align__(16) float g_kp[BH * (T/2) * 20];   // [bh][t/2][d=0..9][2]
__device__ __align__(16) float g_vp[BH * (T/2) * 20];
__device__ __align__(16) float g_attn[BT * 60];

// ================= Kernel 1: QKV projection (R5 version, passing) ==========
__global__ __launch_bounds__(256) void k_qkv(const float* __restrict__ x,
                                             const float* __restrict__ Wqkv) {
    __shared__ __align__(16) float Wsm[180 * 64];   // e-major: [(h*30+e)][d]
    const int tid  = threadIdx.x;
    const int r    = tid & 127;
    const int half = tid >> 7;
    const int row  = blockIdx.x * 128 + r;

    for (int idx = tid; idx < NH*DM*30; idx += 256) {
        int h = idx / (DM*30); int rem = idx % (DM*30);
        int d = rem / 30;      int e   = rem % 30;
        Wsm[(h*30 + e)*64 + d] = Wqkv[idx];
    }
    __syncthreads();

    u64 xp[32];
    {
        const ulonglong2* gx = (const ulonglong2*)(x + row * 64);
        #pragma unroll
        for (int i = 0; i < 16; ++i) { ulonglong2 u = gx[i]; xp[2*i] = u.x; xp[2*i+1] = u.y; }
    }

    const int b = row >> 11, t = row & 2047;
    const int tp = t >> 1, par = t & 1;
    const int ebase = half * 15;

    for (int h = 0; h < NH; ++h) {
        float f[15];
        #pragma unroll
        for (int e = 0; e < 15; ++e) {
            const ulonglong2* w2 = (const ulonglong2*)&Wsm[(h*30 + ebase + e)*64];
            u64 c0, c1, c2, c3;
            {
                ulonglong2 wa = w2[0], wb = w2[1];
                c0 = f2_mul(xp[0], wa.x); c1 = f2_mul(xp[1], wa.y);
                c2 = f2_mul(xp[2], wb.x); c3 = f2_mul(xp[3], wb.y);
            }
            #pragma unroll
            for (int g = 1; g < 8; ++g) {
                ulonglong2 wa = w2[2*g], wb = w2[2*g+1];
                c0 = f2_fma(xp[4*g+0], wa.x, c0);
                c1 = f2_fma(xp[4*g+1], wa.y, c1);
                c2 = f2_fma(xp[4*g+2], wb.x, c2);
                c3 = f2_fma(xp[4*g+3], wb.y, c3);
            }
            c0 = f2_add(c0, c1); c2 = f2_add(c2, c3); c0 = f2_add(c0, c2);
            float l, hh; upk(l, hh, c0);
            f[e] = l + hh;
        }
        const int bh   = b*NH + h;
        const int kvbs = (bh*(T/2) + tp) * 20;
        if (half == 0) {
            const int off = (bh*T + t) * 12;
            float4* oq = (float4*)&g_q[off];
            oq[0] = make_float4(f[0], f[1], f[2], f[3]);
            oq[1] = make_float4(f[4], f[5], f[6], f[7]);
            oq[2] = make_float4(f[8], f[9], 0.f, 0.f);
            #pragma unroll
            for (int d = 0; d < 5; ++d) g_kp[kvbs + 2*d + par] = f[10 + d];
        } else {
            #pragma unroll
            for (int d = 0; d < 5; ++d) g_kp[kvbs + 2*(5+d) + par] = f[d];
            #pragma unroll
            for (int d = 0; d < 10; ++d) g_vp[kvbs + 2*d + par] = f[5 + d];
        }
    }
}

// ====== Kernel 2: causal flash attention (R5 version, passing @246.5) ======
#define ATT_BODY(PHI)                                                          \
    {   const ulonglong2* kp2 = (const ulonglong2*)(ksP + sp*20);              \
        const ulonglong2* vp2 = (const ulonglong2*)(vsP + sp*20);              \
        ulonglong2 kA=kp2[0], kB=kp2[1], kC=kp2[2], kD=kp2[3], kE=kp2[4];      \
        u64 s0 = f2_mul(qp[0], kA.x), s1 = f2_mul(qp[1], kA.y);                \
        s0 = f2_fma(qp[2], kB.x, s0); s1 = f2_fma(qp[3], kB.y, s1);            \
        s0 = f2_fma(qp[4], kC.x, s0); s1 = f2_fma(qp[5], kC.y, s1);            \
        s0 = f2_fma(qp[6], kD.x, s0); s1 = f2_fma(qp[7], kD.y, s1);            \
        s0 = f2_fma(qp[8], kE.x, s0); s1 = f2_fma(qp[9], kE.y, s1);            \
        s0 = f2_add(s0, s1);                                                   \
        float dl, dh; upk(dl, dh, s0);                                         \
        float pl = ex2f(dl);                                                   \
        float ph = PHI;                                                        \
        u64 pp = pk(pl, ph);                                                   \
        ssp = f2_add(ssp, pp);                                                 \
        ulonglong2 vA=vp2[0], vB=vp2[1], vC=vp2[2], vD=vp2[3], vE=vp2[4];      \
        acc[0]=f2_fma(pp,vA.x,acc[0]); acc[1]=f2_fma(pp,vA.y,acc[1]);          \
        acc[2]=f2_fma(pp,vB.x,acc[2]); acc[3]=f2_fma(pp,vB.y,acc[3]);          \
        acc[4]=f2_fma(pp,vC.x,acc[4]); acc[5]=f2_fma(pp,vC.y,acc[5]);          \
        acc[6]=f2_fma(pp,vD.x,acc[6]); acc[7]=f2_fma(pp,vD.y,acc[7]);          \
        acc[8]=f2_fma(pp,vE.x,acc[8]); acc[9]=f2_fma(pp,vE.y,acc[9]); }

__global__ __launch_bounds__(256, 2) void k_attn() {
    __shared__ __align__(16) float ksm[2][1280];
    __shared__ __align__(16) float vsm[2][1280];
    const int tid = threadIdx.x;
    const int bx  = 7 - (int)(blockIdx.x / 48);   // heavy tiles first (LPT)
    const int bh  = blockIdx.x % 48;
    const int q   = bx * 256 + tid;

    u64 qp[10];
    {
        const float4* gq = (const float4*)&g_q[(bh*T + q)*12];
        float4 a = gq[0], b4 = gq[1], c4 = gq[2];
        const float SC = 0.31622776601683794f * 1.4426950408889634f; // rsqrt(10)*log2e
        qp[0]=pk(a.x*SC,a.x*SC);  qp[1]=pk(a.y*SC,a.y*SC);
        qp[2]=pk(a.z*SC,a.z*SC);  qp[3]=pk(a.w*SC,a.w*SC);
        qp[4]=pk(b4.x*SC,b4.x*SC); qp[5]=pk(b4.y*SC,b4.y*SC);
        qp[6]=pk(b4.z*SC,b4.z*SC); qp[7]=pk(b4.w*SC,b4.w*SC);
        qp[8]=pk(c4.x*SC,c4.x*SC); qp[9]=pk(c4.y*SC,c4.y*SC);
    }
    u64 acc[10];
    #pragma unroll
    for (int i = 0; i < 10; ++i) acc[i] = 0ull;
    u64 ssp = 0ull;

    const int nc = 2*bx + 2;
    const float4* srcK0 = (const float4*)&g_kp[(size_t)(bh*(T/2)) * 20];
    const float4* srcV0 = (const float4*)&g_vp[(size_t)(bh*(T/2)) * 20];

    for (int i = tid; i < 640; i += 256) {
        float4 v = (i < 320) ? srcK0[i] : srcV0[i - 320];
        if (i < 320) ((float4*)ksm[0])[i] = v; else ((float4*)vsm[0])[i - 320] = v;
    }
    __syncthreads();

    for (int c = 0; c < nc; ++c) {
        const int cb = c & 1;
        float4 st0, st1, st2;
        const bool more = (c + 1 < nc);
        if (more) {
            const float4* sK = srcK0 + (c+1)*320;
            const float4* sV = srcV0 + (c+1)*320;
            st0 = (tid < 320) ? sK[tid] : sV[tid - 320];
            { int i = tid + 256; st1 = (i < 320) ? sK[i] : sV[i - 320]; }
            if (tid < 128) st2 = sV[tid + 192];
        }

        const float* ksP = ksm[cb];
        const float* vsP = vsm[cb];
        const int rel = q - (c << 7);
        int nf = (rel + 1) >> 1;
        nf = nf < 0 ? 0 : (nf > 64 ? 64 : nf);
        #pragma unroll 2
        for (int sp = 0; sp < nf; ++sp) ATT_BODY(ex2f(dh))
        if ((unsigned)rel < 128u && !(rel & 1)) {
            const int sp = rel >> 1;
            ATT_BODY(0.f)
        }

        if (more) {
            float4* dK = (float4*)ksm[cb ^ 1];
            float4* dV = (float4*)vsm[cb ^ 1];
            if (tid < 320) dK[tid] = st0; else dV[tid - 320] = st0;
            { int i = tid + 256; if (i < 320) dK[i] = st1; else dV[i - 320] = st1; }
            if (tid < 128) dV[tid + 192] = st2;
        }
        __syncthreads();
    }

    float sl, sh; upk(sl, sh, ssp);
    const float inv = 1.f / (sl + sh);
    float* o = &g_attn[((bh/NH)*T + q)*60 + (bh%NH)*10];
    #pragma unroll
    for (int d = 0; d < 10; d += 2) {
        float l0, h0, l1, h1;
        upk(l0, h0, acc[d]); upk(l1, h1, acc[d+1]);
        *(float2*)&o[d] = make_float2((l0 + h0)*inv, (l1 + h1)*inv);
    }
}

// ====== Kernel 3: fused proj + LN1 + FFN + LN2 — 16 rows/block ======
// smem 24.6KB (was 48.5KB) -> more resident CTAs for latency hiding.
#define HSP 260
#define TROWS 16
__global__ __launch_bounds__(256) void k_tail(const float* __restrict__ x,
                                              const float* __restrict__ Wp,
                                              const float* __restrict__ bp,
                                              const float* __restrict__ g1,
                                              const float* __restrict__ b1ln,
                                              const float* __restrict__ W1,
                                              const float* __restrict__ bb1,
                                              const float* __restrict__ W2,
                                              const float* __restrict__ bb2,
                                              const float* __restrict__ g2,
                                              const float* __restrict__ b2ln,
                                              float* __restrict__ out) {
    extern __shared__ __align__(16) float sm[];
    float* atn = sm;                          // 16*60
    float* xs  = sm + TROWS*60;               // 16*64
    float* hs  = sm + TROWS*60 + TROWS*64;    // 16*260

    const int tid  = threadIdx.x;
    const int row0 = blockIdx.x * TROWS;

    for (int idx = tid; idx < TROWS*60; idx += 256) atn[idx] = g_attn[row0*60 + idx];
    __syncthreads();

    // ---- proj + LN1 -> xs : 16 threads/row, 4 cols/thread ----
    {
        const int r  = tid >> 4;
        const int cg = tid & 15;
        const int c0 = cg * 4;
        u64 pa0 = 0, pa1 = 0;
        #pragma unroll 4
        for (int i = 0; i < 60; ++i) {
            float a = atn[r*60 + i];
            u64 ap = pk(a, a);
            const ulonglong2* w2 = (const ulonglong2*)&Wp[i*64 + c0];
            ulonglong2 wA = w2[0];
            pa0 = f2_fma(ap, wA.x, pa0); pa1 = f2_fma(ap, wA.y, pa1);
        }
        {
            const ulonglong2* bb = (const ulonglong2*)&bp[c0];
            ulonglong2 bA = bb[0];
            pa0 = f2_add(pa0, bA.x); pa1 = f2_add(pa1, bA.y);
        }
        float sa[4];
        upk(sa[0], sa[1], pa0); upk(sa[2], sa[3], pa1);
        float s = 0.f, qq = 0.f;
        #pragma unroll
        for (int i = 0; i < 4; ++i) { s += sa[i]; qq = fmaf(sa[i], sa[i], qq); }
        #pragma unroll
        for (int m = 8; m; m >>= 1) {
            s  += __shfl_xor_sync(0xffffffffu, s, m);
            qq += __shfl_xor_sync(0xffffffffu, qq, m);
        }
        const float mu = s * (1.f/64.f);
        const float ri = rsqrtf(qq * (1.f/64.f) - mu*mu + 1e-5f);
        const float4 xA = *(const float4*)(x + (row0 + r)*64 + c0);
        const float4 gA = *(const float4*)(g1 + c0);
        const float4 bA = *(const float4*)(b1ln + c0);
        float4 o0;
        o0.x = xA.x + (sa[0]-mu)*ri*gA.x + bA.x;  o0.y = xA.y + (sa[1]-mu)*ri*gA.y + bA.y;
        o0.z = xA.z + (sa[2]-mu)*ri*gA.z + bA.z;  o0.w = xA.w + (sa[3]-mu)*ri*gA.w + bA.w;
        *(float4*)&xs[r*64 + c0] = o0;
    }
    __syncthreads();

    const int w  = tid >> 5;   // warp 0..7
    const int co = tid & 31;
    const int rb = w * 2;      // 2 rows per warp

    // ---- gemm1: hs = gelu(xs @ W1 + b1) ----
    {
        const int c0 = co * 8;
        u64 ac[2][4];
        #pragma unroll
        for (int r = 0; r < 2; ++r)
            #pragma unroll
            for (int j = 0; j < 4; ++j) ac[r][j] = 0ull;

        for (int d = 0; d < 64; d += 4) {
            float4 xv[2];
            #pragma unroll
            for (int r = 0; r < 2; ++r) xv[r] = *(const float4*)&xs[(rb+r)*64 + d];
            #pragma unroll
            for (int dd = 0; dd < 4; ++dd) {
                const ulonglong2* w1p = (const ulonglong2*)&W1[(d+dd)*256 + c0];
                ulonglong2 wA = w1p[0], wB = w1p[1];
                #pragma unroll
                for (int r = 0; r < 2; ++r) {
                    float xvv = ((const float*)&xv[r])[dd];
                    u64 px = pk(xvv, xvv);
                    ac[r][0] = f2_fma(px, wA.x, ac[r][0]);
                    ac[r][1] = f2_fma(px, wA.y, ac[r][1]);
                    ac[r][2] = f2_fma(px, wB.x, ac[r][2]);
                    ac[r][3] = f2_fma(px, wB.y, ac[r][3]);
                }
            }
        }
        const ulonglong2* bbp = (const ulonglong2*)&bb1[c0];
        ulonglong2 bA = bbp[0], bB = bbp[1];
        #pragma unroll
        for (int r = 0; r < 2; ++r) {
            ac[r][0] = f2_add(ac[r][0], bA.x); ac[r][1] = f2_add(ac[r][1], bA.y);
            ac[r][2] = f2_add(ac[r][2], bB.x); ac[r][3] = f2_add(ac[r][3], bB.y);
            float h[8];
            upk(h[0], h[1], ac[r][0]); upk(h[2], h[3], ac[r][1]);
            upk(h[4], h[5], ac[r][2]); upk(h[6], h[7], ac[r][3]);
            #pragma unroll
            for (int j = 0; j < 8; ++j)
                h[j] = 0.5f * h[j] * (1.f + erff(h[j] * 0.70710678118654752f));
            *(float4*)&hs[(rb+r)*HSP + c0]     = make_float4(h[0], h[1], h[2], h[3]);
            *(float4*)&hs[(rb+r)*HSP + c0 + 4] = make_float4(h[4], h[5], h[6], h[7]);
        }
    }
    __syncthreads();

    // ---- gemm2: ffn = hs @ W2 + b2; LN2; out = xs + LN2(ffn) ----
    {
        const int c = 2 * co;
        u64 bacc[2];
        bacc[0] = 0ull; bacc[1] = 0ull;

        for (int i = 0; i < 256; i += 4) {
            float4 hv[2];
            #pragma unroll
            for (int r = 0; r < 2; ++r) hv[r] = *(const float4*)&hs[(rb+r)*HSP + i];
            #pragma unroll
            for (int ii = 0; ii < 4; ++ii) {
                u64 wv = *(const u64*)&W2[(i+ii)*64 + c];
                #pragma unroll
                for (int r = 0; r < 2; ++r) {
                    float hvv = ((const float*)&hv[r])[ii];
                    u64 ph = pk(hvv, hvv);
                    bacc[r] = f2_fma(ph, wv, bacc[r]);
                }
            }
        }
        u64 b2v = *(const u64*)&bb2[c];
        float fv[2][2];
        #pragma unroll
        for (int r = 0; r < 2; ++r) {
            bacc[r] = f2_add(bacc[r], b2v);
            upk(fv[r][0], fv[r][1], bacc[r]);
        }
        float mu[2], ri[2];
        #pragma unroll
        for (int r = 0; r < 2; ++r) {
            float s = fv[r][0] + fv[r][1];
            float qq = fmaf(fv[r][0], fv[r][0], fv[r][1]*fv[r][1]);
            #pragma unroll
            for (int m = 16; m; m >>= 1) {
                s  += __shfl_xor_sync(0xffffffffu, s, m);
                qq += __shfl_xor_sync(0xffffffffu, qq, m);
            }
            mu[r] = s * (1.f/64.f);
            ri[r] = rsqrtf(qq * (1.f/64.f) - mu[r]*mu[r] + 1e-5f);
        }
        float2 g2v = *(const float2*)&g2[c];
        float2 b2l = *(const float2*)&b2ln[c];
        #pragma unroll
        for (int r = 0; r < 2; ++r) {
            float2 xv = *(const float2*)&xs[(rb+r)*64 + c];
            float2 o;
            o.x = xv.x + (fv[r][0]-mu[r])*ri[r]*g2v.x + b2l.x;
            o.y = xv.y + (fv[r][1]-mu[r])*ri[r]*g2v.y + b2l.y;
            *(float2*)&out[(row0 + rb + r)*64 + c] = o;
        }
    }
}

// ===========================================================================
extern "C" void kernel_launch(void* const* d_in, const int* in_sizes, int n_in,
                              void* d_out, int out_size) {
    const float* x     = (const float*)d_in[0];
    const float* Wqkv  = (const float*)d_in[1];
    const float* Wproj = (const float*)d_in[2];
    const float* bproj = (const float*)d_in[3];
    const float* ln1g  = (const float*)d_in[4];
    const float* ln1b  = (const float*)d_in[5];
    const float* W1    = (const float*)d_in[6];
    const float* b1    = (const float*)d_in[7];
    const float* W2    = (const float*)d_in[8];
    const float* b2    = (const float*)d_in[9];
    const float* ln2g  = (const float*)d_in[10];
    const float* ln2b  = (const float*)d_in[11];
    float* out = (float*)d_out;

    k_qkv<<<BT/128, 256>>>(x, Wqkv);
    k_attn<<<8*48, 256>>>();
    const int smemTail = (TROWS*60 + TROWS*64 + TROWS*HSP) * (int)sizeof(float);
    k_tail<<<BT/TROWS, 256, smemTail>>>(x, Wproj, bproj, ln1g, ln1b,
                                        W1, b1, W2, b2, ln2g, ln2b, out);
}